// round 4
// baseline (speedup 1.0000x reference)
#include <cuda_runtime.h>
#include <cfloat>

// N=8192 tokens, K=4096, D=1024.
//   idx[n] = argmax_k x[n,k]  (first-occurrence tie-break)
//   out[n,d] = W[d, idx[n]]
//
// Single kernel:
//   bids 0..1023      : transpose W [D,K] -> g_Wt [K,D], then release+count.
//   bids 1024..9215   : per-token argmax, acquire-wait for transpose done,
//                       coalesced gather g_Wt[idx] -> out[n].
// Flags self-reset (last argmax block zeroes them) so graph replays are clean.

#define NTOK 8192
#define KDIM 4096
#define DDIM 1024
#define TP_TILE 64
#define TP_BLOCKS ((KDIM / TP_TILE) * (DDIM / TP_TILE))   // 1024

__device__ float g_Wt[(size_t)KDIM * DDIM];   // 16 MB scratch
__device__ int   g_done = 0;                  // transpose blocks completed
__device__ int   g_fin  = 0;                  // argmax blocks completed

__device__ __forceinline__ int ld_acquire_gpu(const int* p) {
    int v;
    asm volatile("ld.acquire.gpu.global.s32 %0, [%1];" : "=r"(v) : "l"(p) : "memory");
    return v;
}

__global__ void __launch_bounds__(256) ste_fused_kernel(
    const float* __restrict__ x, const float* __restrict__ W,
    float* __restrict__ out)
{
    const int bid = blockIdx.x;
    const int tid = threadIdx.x;

    if (bid < TP_BLOCKS) {
        // ---- transpose one 64x64 tile of W [D,K] -> g_Wt [K,D] ----
        __shared__ float t[TP_TILE][TP_TILE + 1];
        const int k0 = (bid % (KDIM / TP_TILE)) * TP_TILE;
        const int d0 = (bid / (KDIM / TP_TILE)) * TP_TILE;
        const int tx = tid & 15;     // float4 lane along fast dim
        const int ty = tid >> 4;     // row 0..15

        #pragma unroll
        for (int i = 0; i < 4; ++i) {
            int r = ty + 16 * i;     // d offset within tile
            float4 v = *reinterpret_cast<const float4*>(
                W + (size_t)(d0 + r) * KDIM + (k0 + 4 * tx));
            t[r][4 * tx + 0] = v.x;
            t[r][4 * tx + 1] = v.y;
            t[r][4 * tx + 2] = v.z;
            t[r][4 * tx + 3] = v.w;
        }
        __syncthreads();

        #pragma unroll
        for (int i = 0; i < 4; ++i) {
            int r = ty + 16 * i;     // k offset within tile
            float4 v;
            v.x = t[4 * tx + 0][r];
            v.y = t[4 * tx + 1][r];
            v.z = t[4 * tx + 2][r];
            v.w = t[4 * tx + 3][r];
            *reinterpret_cast<float4*>(
                g_Wt + (size_t)(k0 + r) * DDIM + (d0 + 4 * tx)) = v;
        }
        __syncthreads();
        if (tid == 0) {
            __threadfence();                 // release this block's Wt stores
            atomicAdd(&g_done, 1);
        }
        return;
    }

    // ---- per-token argmax over x[n, :] ----
    const int n = bid - TP_BLOCKS;
    const float4* xr = reinterpret_cast<const float4*>(x + (size_t)n * KDIM);
    float best = -FLT_MAX;
    int   bi   = 0x7fffffff;

    #pragma unroll
    for (int it = 0; it < (KDIM / 4) / 256; ++it) {
        int c = tid + it * 256;
        float4 v = xr[c];
        int base = c * 4;
        if (v.x > best) { best = v.x; bi = base + 0; }
        if (v.y > best) { best = v.y; bi = base + 1; }
        if (v.z > best) { best = v.z; bi = base + 2; }
        if (v.w > best) { best = v.w; bi = base + 3; }
    }

    // warp reduce (smaller index wins ties)
    #pragma unroll
    for (int off = 16; off > 0; off >>= 1) {
        float ov = __shfl_down_sync(0xffffffffu, best, off);
        int   oi = __shfl_down_sync(0xffffffffu, bi,   off);
        if (ov > best || (ov == best && oi < bi)) { best = ov; bi = oi; }
    }

    // block reduce across 8 warps
    __shared__ float s_val[8];
    __shared__ int   s_idx[8];
    __shared__ int   s_final;
    int warp = tid >> 5;
    int lane = tid & 31;
    if (lane == 0) { s_val[warp] = best; s_idx[warp] = bi; }
    __syncthreads();
    if (warp == 0) {
        best = (lane < 8) ? s_val[lane] : -FLT_MAX;
        bi   = (lane < 8) ? s_idx[lane] : 0x7fffffff;
        #pragma unroll
        for (int off = 4; off > 0; off >>= 1) {
            float ov = __shfl_down_sync(0xffffffffu, best, off);
            int   oi = __shfl_down_sync(0xffffffffu, bi,   off);
            if (ov > best || (ov == best && oi < bi)) { best = ov; bi = oi; }
        }
        if (lane == 0) s_final = bi;
    }
    __syncthreads();
    const int idx = s_final;

    // ---- wait for transpose completion (usually already done) ----
    while (ld_acquire_gpu(&g_done) < TP_BLOCKS) __nanosleep(64);

    // ---- coalesced gather: out[n, :] = g_Wt[idx, :] ----
    const float4* src = reinterpret_cast<const float4*>(g_Wt + (size_t)idx * DDIM);
    float4*       dst = reinterpret_cast<float4*>(out + (size_t)n * DDIM);
    dst[tid] = src[tid];

    // ---- self-reset flags for graph replay ----
    __syncthreads();
    if (tid == 0) {
        int t = atomicAdd(&g_fin, 1);
        if (t == NTOK - 1) {           // last argmax block: everyone passed the wait
            atomicExch(&g_fin, 0);
            atomicExch(&g_done, 0);
        }
    }
}

extern "C" void kernel_launch(void* const* d_in, const int* in_sizes, int n_in,
                              void* d_out, int out_size) {
    const float* x = (const float*)d_in[0];   // [N, K]
    const float* W = (const float*)d_in[1];   // [D, K]
    float* out = (float*)d_out;               // [N, D]

    ste_fused_kernel<<<TP_BLOCKS + NTOK, 256>>>(x, W, out);
}

// round 5
// speedup vs baseline: 1.3142x; 1.3142x over previous
#include <cuda_runtime.h>
#include <cfloat>

// N=8192 tokens, K=4096, D=1024.
//   idx[n] = argmax_k x[n,k]  (first-occurrence tie-break)
//   out[n,d] = W[d, idx[n]]
//
// K1: fast float4 transpose W [D,K] -> g_Wt [K,D] (32 MB r+w, ~6 us).
// K2: fused per-token argmax + coalesced row gather out[n,:] = g_Wt[idx,:]
//     (measured 28.6 us @ 75% DRAM in R1 — the good component, reused).

#define NTOK 8192
#define KDIM 4096
#define DDIM 1024
#define TP_TILE 64
#define TP_BLOCKS ((KDIM / TP_TILE) * (DDIM / TP_TILE))   // 1024

__device__ float g_Wt[(size_t)KDIM * DDIM];   // 16 MB scratch

// ---------------- K1: transpose, float4 both sides ----------------
__global__ void __launch_bounds__(256) transpose_kernel(const float* __restrict__ W)
{
    __shared__ float t[TP_TILE][TP_TILE + 1];
    const int bid = blockIdx.x;
    const int tid = threadIdx.x;
    const int k0 = (bid % (KDIM / TP_TILE)) * TP_TILE;
    const int d0 = (bid / (KDIM / TP_TILE)) * TP_TILE;
    const int tx = tid & 15;     // float4 lane along fast dim
    const int ty = tid >> 4;     // row 0..15

    // load: rows along d, 64 floats along k per row (coalesced float4)
    #pragma unroll
    for (int i = 0; i < 4; ++i) {
        int r = ty + 16 * i;
        float4 v = *reinterpret_cast<const float4*>(
            W + (size_t)(d0 + r) * KDIM + (k0 + 4 * tx));
        t[r][4 * tx + 0] = v.x;
        t[r][4 * tx + 1] = v.y;
        t[r][4 * tx + 2] = v.z;
        t[r][4 * tx + 3] = v.w;
    }
    __syncthreads();

    // store: rows along k, 64 floats along d per row (coalesced float4)
    #pragma unroll
    for (int i = 0; i < 4; ++i) {
        int r = ty + 16 * i;
        float4 v;
        v.x = t[4 * tx + 0][r];
        v.y = t[4 * tx + 1][r];
        v.z = t[4 * tx + 2][r];
        v.w = t[4 * tx + 3][r];
        *reinterpret_cast<float4*>(
            g_Wt + (size_t)(k0 + r) * DDIM + (d0 + 4 * tx)) = v;
    }
}

// ---------------- K2: fused argmax + row gather ----------------
__global__ void __launch_bounds__(256) argmax_gather_kernel(
    const float* __restrict__ x, float* __restrict__ out)
{
    const int n   = blockIdx.x;
    const int tid = threadIdx.x;

    // per-thread argmax over float4 chunks (indices visited in increasing order)
    const float4* xr = reinterpret_cast<const float4*>(x + (size_t)n * KDIM);
    float best = -FLT_MAX;
    int   bi   = 0x7fffffff;

    #pragma unroll
    for (int it = 0; it < (KDIM / 4) / 256; ++it) {
        int c = tid + it * 256;
        float4 v = xr[c];
        int base = c * 4;
        if (v.x > best) { best = v.x; bi = base + 0; }
        if (v.y > best) { best = v.y; bi = base + 1; }
        if (v.z > best) { best = v.z; bi = base + 2; }
        if (v.w > best) { best = v.w; bi = base + 3; }
    }

    // warp reduce (smaller index wins ties)
    #pragma unroll
    for (int off = 16; off > 0; off >>= 1) {
        float ov = __shfl_down_sync(0xffffffffu, best, off);
        int   oi = __shfl_down_sync(0xffffffffu, bi,   off);
        if (ov > best || (ov == best && oi < bi)) { best = ov; bi = oi; }
    }

    // block reduce across 8 warps
    __shared__ float s_val[8];
    __shared__ int   s_idx[8];
    __shared__ int   s_final;
    int warp = tid >> 5;
    int lane = tid & 31;
    if (lane == 0) { s_val[warp] = best; s_idx[warp] = bi; }
    __syncthreads();
    if (warp == 0) {
        best = (lane < 8) ? s_val[lane] : -FLT_MAX;
        bi   = (lane < 8) ? s_idx[lane] : 0x7fffffff;
        #pragma unroll
        for (int off = 4; off > 0; off >>= 1) {
            float ov = __shfl_down_sync(0xffffffffu, best, off);
            int   oi = __shfl_down_sync(0xffffffffu, bi,   off);
            if (ov > best || (ov == best && oi < bi)) { best = ov; bi = oi; }
        }
        if (lane == 0) s_final = bi;
    }
    __syncthreads();
    const int idx = s_final;

    // coalesced row copy: out[n, :] = g_Wt[idx, :]  (256 float4 = 4 KB)
    const float4* src = reinterpret_cast<const float4*>(g_Wt + (size_t)idx * DDIM);
    float4*       dst = reinterpret_cast<float4*>(out + (size_t)n * DDIM);
    dst[tid] = src[tid];
}

extern "C" void kernel_launch(void* const* d_in, const int* in_sizes, int n_in,
                              void* d_out, int out_size) {
    const float* x = (const float*)d_in[0];   // [N, K]
    const float* W = (const float*)d_in[1];   // [D, K]
    float* out = (float*)d_out;               // [N, D]

    transpose_kernel<<<TP_BLOCKS, 256>>>(W);
    argmax_gather_kernel<<<NTOK, 256>>>(x, out);
}

// round 6
// speedup vs baseline: 1.4182x; 1.0791x over previous
#include <cuda_runtime.h>
#include <cfloat>

// N=8192 tokens, K=4096, D=1024.
//   idx[n] = argmax_k x[n,k]  (first-occurrence tie-break)
//   out[n,d] = W[d, idx[n]]
//
// K1: float4 transpose W [D,K] -> g_Wt [K,D]; W read with streaming hint
//     (dead after), Wt stored normally (want it L2-resident for K2).
// K2: fused per-token argmax + row gather. x read with __ldcs (touched once,
//     evict-first) and out written with __stcs so the 16 MB Wt stays hot in
//     L2 and gather reads hit L2 instead of re-fetching from DRAM.

#define NTOK 8192
#define KDIM 4096
#define DDIM 1024
#define TP_TILE 64
#define TP_BLOCKS ((KDIM / TP_TILE) * (DDIM / TP_TILE))   // 1024

__device__ float g_Wt[(size_t)KDIM * DDIM];   // 16 MB scratch

// ---------------- K1: transpose, float4 both sides ----------------
__global__ void __launch_bounds__(256) transpose_kernel(const float* __restrict__ W)
{
    __shared__ float t[TP_TILE][TP_TILE + 1];
    const int bid = blockIdx.x;
    const int tid = threadIdx.x;
    const int k0 = (bid % (KDIM / TP_TILE)) * TP_TILE;
    const int d0 = (bid / (KDIM / TP_TILE)) * TP_TILE;
    const int tx = tid & 15;     // float4 lane along fast dim
    const int ty = tid >> 4;     // row 0..15

    #pragma unroll
    for (int i = 0; i < 4; ++i) {
        int r = ty + 16 * i;
        float4 v = __ldcs(reinterpret_cast<const float4*>(
            W + (size_t)(d0 + r) * KDIM + (k0 + 4 * tx)));
        t[r][4 * tx + 0] = v.x;
        t[r][4 * tx + 1] = v.y;
        t[r][4 * tx + 2] = v.z;
        t[r][4 * tx + 3] = v.w;
    }
    __syncthreads();

    #pragma unroll
    for (int i = 0; i < 4; ++i) {
        int r = ty + 16 * i;
        float4 v;
        v.x = t[4 * tx + 0][r];
        v.y = t[4 * tx + 1][r];
        v.z = t[4 * tx + 2][r];
        v.w = t[4 * tx + 3][r];
        *reinterpret_cast<float4*>(
            g_Wt + (size_t)(k0 + r) * DDIM + (d0 + 4 * tx)) = v;
    }
}

// ---------------- K2: fused argmax + row gather ----------------
__global__ void __launch_bounds__(256) argmax_gather_kernel(
    const float* __restrict__ x, float* __restrict__ out)
{
    const int n   = blockIdx.x;
    const int tid = threadIdx.x;

    // per-thread argmax; x read with streaming (evict-first) hint
    const float4* xr = reinterpret_cast<const float4*>(x + (size_t)n * KDIM);
    float best = -FLT_MAX;
    int   bi   = 0x7fffffff;

    #pragma unroll
    for (int it = 0; it < (KDIM / 4) / 256; ++it) {
        int c = tid + it * 256;
        float4 v = __ldcs(xr + c);
        int base = c * 4;
        if (v.x > best) { best = v.x; bi = base + 0; }
        if (v.y > best) { best = v.y; bi = base + 1; }
        if (v.z > best) { best = v.z; bi = base + 2; }
        if (v.w > best) { best = v.w; bi = base + 3; }
    }

    // warp reduce (smaller index wins ties)
    #pragma unroll
    for (int off = 16; off > 0; off >>= 1) {
        float ov = __shfl_down_sync(0xffffffffu, best, off);
        int   oi = __shfl_down_sync(0xffffffffu, bi,   off);
        if (ov > best || (ov == best && oi < bi)) { best = ov; bi = oi; }
    }

    // block reduce across 8 warps
    __shared__ float s_val[8];
    __shared__ int   s_idx[8];
    __shared__ int   s_final;
    int warp = tid >> 5;
    int lane = tid & 31;
    if (lane == 0) { s_val[warp] = best; s_idx[warp] = bi; }
    __syncthreads();
    if (warp == 0) {
        best = (lane < 8) ? s_val[lane] : -FLT_MAX;
        bi   = (lane < 8) ? s_idx[lane] : 0x7fffffff;
        #pragma unroll
        for (int off = 4; off > 0; off >>= 1) {
            float ov = __shfl_down_sync(0xffffffffu, best, off);
            int   oi = __shfl_down_sync(0xffffffffu, bi,   off);
            if (ov > best || (ov == best && oi < bi)) { best = ov; bi = oi; }
        }
        if (lane == 0) s_final = bi;
    }
    __syncthreads();
    const int idx = s_final;

    // row copy: Wt read normally (want L2 hits), out stored streaming
    const float4* src = reinterpret_cast<const float4*>(g_Wt + (size_t)idx * DDIM);
    float4*       dst = reinterpret_cast<float4*>(out + (size_t)n * DDIM);
    __stcs(dst + tid, src[tid]);
}

extern "C" void kernel_launch(void* const* d_in, const int* in_sizes, int n_in,
                              void* d_out, int out_size) {
    const float* x = (const float*)d_in[0];   // [N, K]
    const float* W = (const float*)d_in[1];   // [D, K]
    float* out = (float*)d_out;               // [N, D]

    transpose_kernel<<<TP_BLOCKS, 256>>>(W);
    argmax_gather_kernel<<<NTOK, 256>>>(x, out);
}